// round 14
// baseline (speedup 1.0000x reference)
#include <cuda_runtime.h>
#include <cuda_fp16.h>
#include <math.h>
#include <stdint.h>

#define Nn   65536
#define Bg   64
#define NPG  1024
#define Ag   32
#define HIDN 128
#define Eg   262144
#define Lg   3
#define NEG  0.2f

// ---------------- scratch (device globals; no allocation allowed) ----------------
// g_deg relies on BSS zero-init for the first call; k_scan1 re-zeroes after use.
__device__ float  g_h[Nn * HIDN];
__device__ __half g_xlh[Nn * HIDN];
__device__ __half g_xrh[Nn * HIDN];
__device__ __half g_w1h[HIDN * HIDN];
__device__ __half g_w2h[HIDN * HIDN];
__device__ int    g_indptr[Nn + 1];
__device__ int    g_cursor[Nn];
__device__ int    g_deg[Nn];
__device__ int    g_blocksum[256];
__device__ int    g_blockoff[256];
__device__ int    g_csr_src[Eg];
__device__ float  g_csr_ea[Eg];
__device__ float  g_partial[1024];
__device__ float  g_ea_mean;
__device__ float  g_pool_sum[Bg * HIDN];
__device__ float  g_pool_max[Bg * HIDN];

__device__ __forceinline__ float4 h4_to_f4(uint2 u) {
    __half2 a = *(__half2*)&u.x;
    __half2 b = *(__half2*)&u.y;
    float2 fa = __half22float2(a);
    float2 fb = __half22float2(b);
    return make_float4(fa.x, fa.y, fb.x, fb.y);
}
__device__ __forceinline__ void cp16(uint32_t dst, const void* src) {
    asm volatile("cp.async.cg.shared.global [%0], [%1], 16;" :: "r"(dst), "l"(src));
}

// ---------------- launch 1: fused h0-init + degree histogram + edge_attr mean ----------------
__global__ void k_prep(const float* __restrict__ x, const float* __restrict__ Wn,
                       const float* __restrict__ bn,
                       const int* __restrict__ ei, const float* __restrict__ ea) {
    int idx = blockIdx.x * 256 + threadIdx.x;
    {
        int node = idx >> 5;
        int c = (idx & 31) << 2;
        float xv = x[node];
        float4 w = *(const float4*)(Wn + c);
        float4 b = *(const float4*)(bn + c);
        float4 o;
        o.x = fmaxf(fmaf(xv, w.x, b.x), 0.f);
        o.y = fmaxf(fmaf(xv, w.y, b.y), 0.f);
        o.z = fmaxf(fmaf(xv, w.z, b.z), 0.f);
        o.w = fmaxf(fmaf(xv, w.w, b.w), 0.f);
        *(float4*)(g_h + node * HIDN + c) = o;
    }
    if (blockIdx.x < Eg / 256) {
        __shared__ float red[256];
        atomicAdd(&g_deg[ei[Eg + idx]], 1);
        red[threadIdx.x] = ea[idx];
        __syncthreads();
        for (int st = 128; st > 0; st >>= 1) {
            if (threadIdx.x < st) red[threadIdx.x] += red[threadIdx.x + st];
            __syncthreads();
        }
        if (threadIdx.x == 0) g_partial[blockIdx.x] = red[0];
    }
}

// ---------------- W converter: W[k][n] -> WT[n][k] fp16 ----------------
__global__ void k_wconv(const float* __restrict__ W1, const float* __restrict__ W2) {
    int idx = blockIdx.x * 256 + threadIdx.x;
    int k = idx >> 7, n = idx & 127;
    g_w1h[n * HIDN + k] = __float2half(W1[idx]);
    g_w2h[n * HIDN + k] = __float2half(W2[idx]);
}

// ---------------- HMMA dual GEMM, cp.async staging + overlapped restage (2 CTAs/SM) ----------------
#define SPITCH 136
__global__ __launch_bounds__(256, 2) void k_gemm_mma(const float* __restrict__ b1,
                                                     const float* __restrict__ b2) {
    extern __shared__ __half smh[];
    __half* sA = smh;                    // [128][136]
    __half* sB = sA + 128 * SPITCH;      // [128][136]

    const int tid  = threadIdx.x;
    const int row0 = blockIdx.x * 128;
    const int srow = tid >> 1, sc0 = (tid & 1) * 64;

    uint32_t smem_u32;
    asm("{ .reg .u64 t; cvta.to.shared.u64 t, %1; cvt.u32.u64 %0, t; }"
        : "=r"(smem_u32) : "l"(smh));
    const uint32_t aBase = smem_u32;
    const uint32_t bBase = smem_u32 + 128 * SPITCH * 2;
    const uint32_t bRowAddr = bBase + (uint32_t)(srow * SPITCH + sc0) * 2;

    {
        const __half* s1 = g_w1h + srow * HIDN + sc0;
        #pragma unroll
        for (int j = 0; j < 64; j += 8)
            cp16(bRowAddr + j * 2, s1 + j);
        asm volatile("cp.async.commit_group;");

        const float* srcA = g_h + (size_t)(row0 + srow) * HIDN + sc0;
        __half* dA = sA + srow * SPITCH + sc0;
        #pragma unroll
        for (int j = 0; j < 64; j += 8) {
            float4 f0 = *(const float4*)(srcA + j);
            float4 f1 = *(const float4*)(srcA + j + 4);
            uint4 u;
            *(__half2*)&u.x = __floats2half2_rn(f0.x, f0.y);
            *(__half2*)&u.y = __floats2half2_rn(f0.z, f0.w);
            *(__half2*)&u.z = __floats2half2_rn(f1.x, f1.y);
            *(__half2*)&u.w = __floats2half2_rn(f1.z, f1.w);
            *(uint4*)(dA + j) = u;
        }
        asm volatile("cp.async.wait_group 0;");
    }
    __syncthreads();

    const int warp = tid >> 5, lane = tid & 31;
    const int mrow = (warp & 3) * 32;
    const int ncol = (warp >> 2) * 64;

    const int l7   = lane & 7;
    const int rsel = ((lane >> 3) & 1) * 8;
    const int csel = (lane >> 4) * 8;
    uint32_t aOff[2];
    #pragma unroll
    for (int m = 0; m < 2; m++)
        aOff[m] = aBase + (uint32_t)((mrow + m * 16 + l7 + rsel) * SPITCH + csel) * 2;
    const int bRow = l7 + (lane >> 4) * 8;
    const int bCol = ((lane >> 3) & 1) * 8;
    uint32_t bOff[4];
    #pragma unroll
    for (int np = 0; np < 4; np++)
        bOff[np] = bBase + (uint32_t)((ncol + np * 16 + bRow) * SPITCH + bCol) * 2;

    #pragma unroll
    for (int mat = 0; mat < 2; mat++) {
        const float* bias = mat ? b2 : b1;
        __half* dst       = mat ? g_xrh : g_xlh;

        float acc[2][8][4];
        #pragma unroll
        for (int m = 0; m < 2; m++)
            #pragma unroll
            for (int n = 0; n < 8; n++)
                #pragma unroll
                for (int q = 0; q < 4; q++) acc[m][n][q] = 0.f;

        #pragma unroll
        for (int k0 = 0; k0 < 128; k0 += 16) {
            uint32_t a[2][4];
            #pragma unroll
            for (int m = 0; m < 2; m++)
                asm volatile("ldmatrix.sync.aligned.m8n8.x4.shared.b16 {%0,%1,%2,%3}, [%4];"
                    : "=r"(a[m][0]), "=r"(a[m][1]), "=r"(a[m][2]), "=r"(a[m][3])
                    : "r"(aOff[m] + k0 * 2));
            uint32_t b[8][2];
            #pragma unroll
            for (int np = 0; np < 4; np++) {
                uint32_t r0, r1, r2, r3;
                asm volatile("ldmatrix.sync.aligned.m8n8.x4.shared.b16 {%0,%1,%2,%3}, [%4];"
                    : "=r"(r0), "=r"(r1), "=r"(r2), "=r"(r3)
                    : "r"(bOff[np] + k0 * 2));
                b[np * 2][0] = r0; b[np * 2][1] = r1;
                b[np * 2 + 1][0] = r2; b[np * 2 + 1][1] = r3;
            }
            #pragma unroll
            for (int m = 0; m < 2; m++)
                #pragma unroll
                for (int n = 0; n < 8; n++)
                    asm volatile(
                        "mma.sync.aligned.m16n8k16.row.col.f32.f16.f16.f32 "
                        "{%0,%1,%2,%3}, {%4,%5,%6,%7}, {%8,%9}, {%0,%1,%2,%3};"
                        : "+f"(acc[m][n][0]), "+f"(acc[m][n][1]),
                          "+f"(acc[m][n][2]), "+f"(acc[m][n][3])
                        : "r"(a[m][0]), "r"(a[m][1]), "r"(a[m][2]), "r"(a[m][3]),
                          "r"(b[n][0]), "r"(b[n][1]));
        }

        if (mat == 0) {
            __syncthreads();
            const __half* s2 = g_w2h + srow * HIDN + sc0;
            #pragma unroll
            for (int j = 0; j < 64; j += 8)
                cp16(bRowAddr + j * 2, s2 + j);
            asm volatile("cp.async.commit_group;");
        }

        const int gid = lane >> 2, t4 = lane & 3;
        #pragma unroll
        for (int m = 0; m < 2; m++) {
            #pragma unroll
            for (int n = 0; n < 8; n++) {
                int col = ncol + n * 8 + t4 * 2;
                float bx = __ldg(&bias[col]), by = __ldg(&bias[col + 1]);
                int r0w = row0 + mrow + m * 16 + gid;
                *(__half2*)(dst + (size_t)r0w * HIDN + col) =
                    __floats2half2_rn(acc[m][n][0] + bx, acc[m][n][1] + by);
                *(__half2*)(dst + (size_t)(r0w + 8) * HIDN + col) =
                    __floats2half2_rn(acc[m][n][2] + bx, acc[m][n][3] + by);
            }
        }

        if (mat == 0) {
            asm volatile("cp.async.wait_group 0;");
            __syncthreads();
        }
    }
}

// ---------------- scan stage 1 ----------------
__global__ void k_scan1() {
    __shared__ int sc[256];
    int node = blockIdx.x * 256 + threadIdx.x;
    int d = g_deg[node];
    g_deg[node] = 0;
    sc[threadIdx.x] = d;
    __syncthreads();
    for (int off = 1; off < 256; off <<= 1) {
        int v = (threadIdx.x >= off) ? sc[threadIdx.x - off] : 0;
        __syncthreads();
        sc[threadIdx.x] += v;
        __syncthreads();
    }
    g_cursor[node] = sc[threadIdx.x] - d;
    if (threadIdx.x == 255) g_blocksum[blockIdx.x] = sc[255];
}

// ---------------- scan stage 2 ----------------
__global__ void k_scan2() {
    __shared__ int   sc[256];
    __shared__ float red[256];
    int t = threadIdx.x;
    int d = g_blocksum[t];
    sc[t] = d;
    float fs = g_partial[t] + g_partial[t + 256] + g_partial[t + 512] + g_partial[t + 768];
    red[t] = fs;
    __syncthreads();
    for (int off = 1; off < 256; off <<= 1) {
        int v = (t >= off) ? sc[t - off] : 0;
        __syncthreads();
        sc[t] += v;
        __syncthreads();
    }
    g_blockoff[t] = sc[t] - d;
    for (int st = 128; st > 0; st >>= 1) {
        if (t < st) red[t] += red[t + st];
        __syncthreads();
    }
    if (t == 0) g_ea_mean = red[0] / (float)Eg;
}

// ---------------- scan stage 3 ----------------
__global__ void k_scan3() {
    int idx = blockIdx.x * 1024 + threadIdx.x;
    int v = g_cursor[idx] + g_blockoff[idx >> 8];
    g_indptr[idx] = v;
    g_cursor[idx] = v;
    if (idx == 0) g_indptr[Nn] = Eg;
}

// ---------------- CSR fill + zero pool accumulators ----------------
__global__ void k_fill(const int* __restrict__ ei, const float* __restrict__ ea) {
    int e = blockIdx.x * blockDim.x + threadIdx.x;
    if (e < Bg * HIDN) { g_pool_sum[e] = 0.f; g_pool_max[e] = 0.f; }
    if (e < Eg) {
        int d = ei[Eg + e];
        int pos = atomicAdd(&g_cursor[d], 1);
        g_csr_src[pos] = ei[e];
        g_csr_ea[pos]  = ea[e];
    }
}

// ---------------- edge aggregation: TWO nodes per warp, interleaved chains ----------------
// lane layout per node (shared): base = (lane>>3)*32 + (lane&7)*4 (4 ch/lane)
// warp handles nodes nA = 2*w, nB = 2*w+1; edges predicated so shuffles stay uniform.
__global__ __launch_bounds__(256) void k_edge(const float* __restrict__ We,
                                              const float* __restrict__ att,
                                              const float* __restrict__ gb) {
    int w    = (blockIdx.x * blockDim.x + threadIdx.x) >> 5;
    int lane = threadIdx.x & 31;
    const int nA = w * 2, nB = nA + 1;
    const int base = ((lane >> 3) << 5) + ((lane & 7) << 2);

    const float4 We4  = *(const float4*)(We + base);
    const float4 att4 = *(const float4*)(att + base);
    const float4 xrA = h4_to_f4(*(const uint2*)(g_xrh + (size_t)nA * HIDN + base));
    const float4 xlA = h4_to_f4(*(const uint2*)(g_xlh + (size_t)nA * HIDN + base));
    const float4 xrB = h4_to_f4(*(const uint2*)(g_xrh + (size_t)nB * HIDN + base));
    const float4 xlB = h4_to_f4(*(const uint2*)(g_xlh + (size_t)nB * HIDN + base));
    const float  eam = g_ea_mean;

    // self logits (two interleaved chains)
    float mA, mB;
    {
        float v, pA, pB;
        v = fmaf(eam, We4.x, xlA.x + xrA.x); v = v > 0.f ? v : NEG * v; pA = v * att4.x;
        v = fmaf(eam, We4.x, xlB.x + xrB.x); v = v > 0.f ? v : NEG * v; pB = v * att4.x;
        v = fmaf(eam, We4.y, xlA.y + xrA.y); v = v > 0.f ? v : NEG * v; pA = fmaf(v, att4.y, pA);
        v = fmaf(eam, We4.y, xlB.y + xrB.y); v = v > 0.f ? v : NEG * v; pB = fmaf(v, att4.y, pB);
        v = fmaf(eam, We4.z, xlA.z + xrA.z); v = v > 0.f ? v : NEG * v; pA = fmaf(v, att4.z, pA);
        v = fmaf(eam, We4.z, xlB.z + xrB.z); v = v > 0.f ? v : NEG * v; pB = fmaf(v, att4.z, pB);
        v = fmaf(eam, We4.w, xlA.w + xrA.w); v = v > 0.f ? v : NEG * v; pA = fmaf(v, att4.w, pA);
        v = fmaf(eam, We4.w, xlB.w + xrB.w); v = v > 0.f ? v : NEG * v; pB = fmaf(v, att4.w, pB);
        pA += __shfl_xor_sync(0xffffffffu, pA, 4);
        pB += __shfl_xor_sync(0xffffffffu, pB, 4);
        pA += __shfl_xor_sync(0xffffffffu, pA, 2);
        pB += __shfl_xor_sync(0xffffffffu, pB, 2);
        pA += __shfl_xor_sync(0xffffffffu, pA, 1);
        pB += __shfl_xor_sync(0xffffffffu, pB, 1);
        mA = pA; mB = pB;
    }
    float  sA = 1.f, sB = 1.f;
    float4 accA = xlA, accB = xlB;

    const int e0A = g_indptr[nA], e1A = g_indptr[nA + 1];
    const int e0B = g_indptr[nB], e1B = g_indptr[nB + 1];
    const int cA = e1A - e0A, cB = e1B - e0B;
    const int iters = (((cA > cB) ? cA : cB) + 1) >> 1;

    for (int i = 0; i < iters; i++) {
        int eA = e0A + 2 * i, eB = e0B + 2 * i;
        bool vA0 = eA < e1A,     vA1 = eA + 1 < e1A;
        bool vB0 = eB < e1B,     vB1 = eB + 1 < e1B;
        int iA0 = vA0 ? eA : 0,  iA1 = vA1 ? eA + 1 : 0;
        int iB0 = vB0 ? eB : 0,  iB1 = vB1 ? eB + 1 : 0;

        int   sa0 = g_csr_src[iA0], sa1 = g_csr_src[iA1];
        int   sb0 = g_csr_src[iB0], sb1 = g_csr_src[iB1];
        float aa0 = g_csr_ea[iA0],  aa1 = g_csr_ea[iA1];
        float ab0 = g_csr_ea[iB0],  ab1 = g_csr_ea[iB1];
        float4 xA0 = h4_to_f4(__ldg((const uint2*)(g_xlh + (size_t)sa0 * HIDN + base)));
        float4 xA1 = h4_to_f4(__ldg((const uint2*)(g_xlh + (size_t)sa1 * HIDN + base)));
        float4 xB0 = h4_to_f4(__ldg((const uint2*)(g_xlh + (size_t)sb0 * HIDN + base)));
        float4 xB1 = h4_to_f4(__ldg((const uint2*)(g_xlh + (size_t)sb1 * HIDN + base)));

        float v, qA0, qA1, qB0, qB1;
        v = fmaf(aa0, We4.x, xA0.x + xrA.x); v = v > 0.f ? v : NEG * v; qA0 = v * att4.x;
        v = fmaf(aa1, We4.x, xA1.x + xrA.x); v = v > 0.f ? v : NEG * v; qA1 = v * att4.x;
        v = fmaf(ab0, We4.x, xB0.x + xrB.x); v = v > 0.f ? v : NEG * v; qB0 = v * att4.x;
        v = fmaf(ab1, We4.x, xB1.x + xrB.x); v = v > 0.f ? v : NEG * v; qB1 = v * att4.x;
        v = fmaf(aa0, We4.y, xA0.y + xrA.y); v = v > 0.f ? v : NEG * v; qA0 = fmaf(v, att4.y, qA0);
        v = fmaf(aa1, We4.y, xA1.y + xrA.y); v = v > 0.f ? v : NEG * v; qA1 = fmaf(v, att4.y, qA1);
        v = fmaf(ab0, We4.y, xB0.y + xrB.y); v = v > 0.f ? v : NEG * v; qB0 = fmaf(v, att4.y, qB0);
        v = fmaf(ab1, We4.y, xB1.y + xrB.y); v = v > 0.f ? v : NEG * v; qB1 = fmaf(v, att4.y, qB1);
        v = fmaf(aa0, We4.z, xA0.z + xrA.z); v = v > 0.f ? v : NEG * v; qA0 = fmaf(v, att4.z, qA0);
        v = fmaf(aa1, We4.z, xA1.z + xrA.z); v = v > 0.f ? v : NEG * v; qA1 = fmaf(v, att4.z, qA1);
        v = fmaf(ab0, We4.z, xB0.z + xrB.z); v = v > 0.f ? v : NEG * v; qB0 = fmaf(v, att4.z, qB0);
        v = fmaf(ab1, We4.z, xB1.z + xrB.z); v = v > 0.f ? v : NEG * v; qB1 = fmaf(v, att4.z, qB1);
        v = fmaf(aa0, We4.w, xA0.w + xrA.w); v = v > 0.f ? v : NEG * v; qA0 = fmaf(v, att4.w, qA0);
        v = fmaf(aa1, We4.w, xA1.w + xrA.w); v = v > 0.f ? v : NEG * v; qA1 = fmaf(v, att4.w, qA1);
        v = fmaf(ab0, We4.w, xB0.w + xrB.w); v = v > 0.f ? v : NEG * v; qB0 = fmaf(v, att4.w, qB0);
        v = fmaf(ab1, We4.w, xB1.w + xrB.w); v = v > 0.f ? v : NEG * v; qB1 = fmaf(v, att4.w, qB1);

        qA0 += __shfl_xor_sync(0xffffffffu, qA0, 4);
        qA1 += __shfl_xor_sync(0xffffffffu, qA1, 4);
        qB0 += __shfl_xor_sync(0xffffffffu, qB0, 4);
        qB1 += __shfl_xor_sync(0xffffffffu, qB1, 4);
        qA0 += __shfl_xor_sync(0xffffffffu, qA0, 2);
        qA1 += __shfl_xor_sync(0xffffffffu, qA1, 2);
        qB0 += __shfl_xor_sync(0xffffffffu, qB0, 2);
        qB1 += __shfl_xor_sync(0xffffffffu, qB1, 2);
        qA0 += __shfl_xor_sync(0xffffffffu, qA0, 1);
        qA1 += __shfl_xor_sync(0xffffffffu, qA1, 1);
        qB0 += __shfl_xor_sync(0xffffffffu, qB0, 1);
        qB1 += __shfl_xor_sync(0xffffffffu, qB1, 1);

        float pA0 = vA0 ? __expf(qA0 - mA) : 0.f;
        float pA1 = vA1 ? __expf(qA1 - mA) : 0.f;
        float pB0 = vB0 ? __expf(qB0 - mB) : 0.f;
        float pB1 = vB1 ? __expf(qB1 - mB) : 0.f;
        sA += pA0 + pA1;
        sB += pB0 + pB1;
        accA.x = fmaf(pA0, xA0.x, fmaf(pA1, xA1.x, accA.x));
        accA.y = fmaf(pA0, xA0.y, fmaf(pA1, xA1.y, accA.y));
        accA.z = fmaf(pA0, xA0.z, fmaf(pA1, xA1.z, accA.z));
        accA.w = fmaf(pA0, xA0.w, fmaf(pA1, xA1.w, accA.w));
        accB.x = fmaf(pB0, xB0.x, fmaf(pB1, xB1.x, accB.x));
        accB.y = fmaf(pB0, xB0.y, fmaf(pB1, xB1.y, accB.y));
        accB.z = fmaf(pB0, xB0.z, fmaf(pB1, xB1.z, accB.z));
        accB.w = fmaf(pB0, xB0.w, fmaf(pB1, xB1.w, accB.w));
    }

    const float4 gb4 = *(const float4*)(gb + base);
    {
        const float inv = 1.f / sA;
        const float4 h4 = *(const float4*)(g_h + (size_t)nA * HIDN + base);
        float4 o;
        o.x = fmaxf(fmaf(accA.x, inv, gb4.x), 0.f) + h4.x;
        o.y = fmaxf(fmaf(accA.y, inv, gb4.y), 0.f) + h4.y;
        o.z = fmaxf(fmaf(accA.z, inv, gb4.z), 0.f) + h4.z;
        o.w = fmaxf(fmaf(accA.w, inv, gb4.w), 0.f) + h4.w;
        *(float4*)(g_h + (size_t)nA * HIDN + base) = o;
    }
    {
        const float inv = 1.f / sB;
        const float4 h4 = *(const float4*)(g_h + (size_t)nB * HIDN + base);
        float4 o;
        o.x = fmaxf(fmaf(accB.x, inv, gb4.x), 0.f) + h4.x;
        o.y = fmaxf(fmaf(accB.y, inv, gb4.y), 0.f) + h4.y;
        o.z = fmaxf(fmaf(accB.z, inv, gb4.z), 0.f) + h4.z;
        o.w = fmaxf(fmaf(accB.w, inv, gb4.w), 0.f) + h4.w;
        *(float4*)(g_h + (size_t)nB * HIDN + base) = o;
    }
}

// ---------------- pooling (h >= 0, int-bit atomicMax valid) ----------------
__global__ void k_pool() {
    int b = blockIdx.x >> 3;
    int chunk = blockIdx.x & 7;
    int j = threadIdx.x;
    int node0 = b * NPG + chunk * 128;
    float s = 0.f, mx = 0.f;
    #pragma unroll 4
    for (int t = 0; t < 128; t++) {
        float v = g_h[(size_t)(node0 + t) * HIDN + j];
        s += v;
        mx = fmaxf(mx, v);
    }
    atomicAdd(&g_pool_sum[b * HIDN + j], s);
    atomicMax((int*)&g_pool_max[b * HIDN + j], __float_as_int(mx));
}

// ---------------- fused action encoder + Q head ----------------
__global__ __launch_bounds__(256) void k_head(const float* __restrict__ at,
        const float* __restrict__ aW1, const float* __restrict__ ab1,
        const float* __restrict__ aW2, const float* __restrict__ ab2,
        const float* __restrict__ qW1, const float* __restrict__ qb1,
        const float* __restrict__ qW2, const float* __restrict__ qb2,
        const float* __restrict__ qW3, const float* __restrict__ qb3,
        float* __restrict__ out) {
    extern __shared__ float sm[];
    float* IN   = sm;
    float* S1   = IN + 16 * 516;
    float* S2   = S1 + 16 * 128;
    float* tcol = S2 + 16 * 128;
    float* ps   = tcol + 128;
    float* pm   = ps + 128;

    const int tid = threadIdx.x;
    const int b   = blockIdx.x >> 1;
    const int a0  = (blockIdx.x & 1) * 16;

    if (tid < 128) {
        ps[tid] = g_pool_sum[b * HIDN + tid];
        pm[tid] = g_pool_max[b * HIDN + tid];
    }
    __syncthreads();

    for (int idx = tid; idx < 16 * 512; idx += 256) {
        int a = idx >> 9, q = idx & 511;
        int slot = q >> 7, col = q & 127;
        int node = (int)at[(size_t)(b * Ag + a0 + a) * 7 + slot] + b * NPG;
        IN[a * 516 + q] = g_h[(size_t)node * HIDN + col];
    }
    for (int idx = tid; idx < 16 * 3; idx += 256) {
        int a = idx / 3, ms = idx % 3;
        IN[a * 516 + 512 + ms] = at[(size_t)(b * Ag + a0 + a) * 7 + 4 + ms];
    }
    if (tid < 128) {
        float acc = qb1[tid];
        for (int k = 0; k < 128; k++) {
            float sv = ps[k];
            acc = fmaf(sv, qW1[k * 128 + tid], acc);
            acc = fmaf(sv * (1.f / 1024.f), qW1[(128 + k) * 128 + tid], acc);
            acc = fmaf(pm[k], qW1[(256 + k) * 128 + tid], acc);
        }
        tcol[tid] = acc;
    }
    __syncthreads();

    const int col = tid & 127;
    const int ab  = (tid >> 7) * 8;

    {
        float acc[8]; float bias = ab1[col];
        #pragma unroll
        for (int a = 0; a < 8; a++) acc[a] = bias;
        for (int k = 0; k < 515; k++) {
            float w = aW1[k * 128 + col];
            #pragma unroll
            for (int a = 0; a < 8; a++) acc[a] = fmaf(IN[(ab + a) * 516 + k], w, acc[a]);
        }
        #pragma unroll
        for (int a = 0; a < 8; a++) S1[(ab + a) * 128 + col] = fmaxf(acc[a], 0.f);
    }
    __syncthreads();
    {
        float acc[8]; float bias = ab2[col];
        #pragma unroll
        for (int a = 0; a < 8; a++) acc[a] = bias;
        for (int k = 0; k < 128; k++) {
            float w = aW2[k * 128 + col];
            #pragma unroll
            for (int a = 0; a < 8; a++) acc[a] = fmaf(S1[(ab + a) * 128 + k], w, acc[a]);
        }
        #pragma unroll
        for (int a = 0; a < 8; a++) S2[(ab + a) * 128 + col] = fmaxf(acc[a], 0.f);
    }
    __syncthreads();
    {
        float acc[8]; float t = tcol[col];
        #pragma unroll
        for (int a = 0; a < 8; a++) acc[a] = t;
        for (int k = 0; k < 128; k++) {
            float w = qW1[(384 + k) * 128 + col];
            #pragma unroll
            for (int a = 0; a < 8; a++) acc[a] = fmaf(S2[(ab + a) * 128 + k], w, acc[a]);
        }
        #pragma unroll
        for (int a = 0; a < 8; a++) S1[(ab + a) * 128 + col] = fmaxf(acc[a], 0.f);
    }
    __syncthreads();
    {
        float acc[8]; float bias = qb2[col];
        #pragma unroll
        for (int a = 0; a < 8; a++) acc[a] = bias;
        for (int k = 0; k < 128; k++) {
            float w = qW2[k * 128 + col];
            #pragma unroll
            for (int a = 0; a < 8; a++) acc[a] = fmaf(S1[(ab + a) * 128 + k], w, acc[a]);
        }
        #pragma unroll
        for (int a = 0; a < 8; a++) S2[(ab + a) * 128 + col] = fmaxf(acc[a], 0.f);
    }
    __syncthreads();
    {
        int w_id = tid >> 5, lane = tid & 31;
        for (int a = w_id; a < 16; a += 8) {
            float s = 0.f;
            #pragma unroll
            for (int kk = 0; kk < 4; kk++)
                s = fmaf(S2[a * 128 + kk * 32 + lane], qW3[kk * 32 + lane], s);
            #pragma unroll
            for (int o = 16; o > 0; o >>= 1) s += __shfl_xor_sync(0xffffffffu, s, o);
            if (lane == 0) out[b * Ag + a0 + a] = s + qb3[0];
        }
    }
}

// ---------------- launch ----------------
extern "C" void kernel_launch(void* const* d_in, const int* in_sizes, int n_in,
                              void* d_out, int out_size) {
    const float *x, *edge_attr, *action_tensor;
    const float *Wn, *bn, *gWl, *gbl, *gWr, *gbr, *gWe, *gatt, *gb;
    const float *aW1, *ab1, *aW2, *ab2, *qW1, *qb1, *qW2, *qb2, *qW3, *qb3;
    const int* edge_index;

    x             = (const float*)d_in[0];
    edge_attr     = (const float*)d_in[1];
    action_tensor = (const float*)d_in[2];

    if (in_sizes[3] > 100000) {
        edge_index = (const int*)d_in[3];
        Wn  = (const float*)d_in[6];  bn  = (const float*)d_in[7];
        gWl = (const float*)d_in[8];  gWr = (const float*)d_in[9];
        gWe = (const float*)d_in[10]; gatt= (const float*)d_in[11];
        gbl = (const float*)d_in[12]; gbr = (const float*)d_in[13];
        gb  = (const float*)d_in[14];
        aW1 = (const float*)d_in[15]; ab1 = (const float*)d_in[16];
        aW2 = (const float*)d_in[17]; ab2 = (const float*)d_in[18];
        qW1 = (const float*)d_in[19]; qb1 = (const float*)d_in[20];
        qW2 = (const float*)d_in[21]; qb2 = (const float*)d_in[22];
        qW3 = (const float*)d_in[23]; qb3 = (const float*)d_in[24];
    } else {
        Wn  = (const float*)d_in[3];  bn  = (const float*)d_in[4];
        gWl = (const float*)d_in[5];  gbl = (const float*)d_in[6];
        gWr = (const float*)d_in[7];  gbr = (const float*)d_in[8];
        gWe = (const float*)d_in[9];  gatt= (const float*)d_in[10];
        gb  = (const float*)d_in[11];
        aW1 = (const float*)d_in[12]; ab1 = (const float*)d_in[13];
        aW2 = (const float*)d_in[14]; ab2 = (const float*)d_in[15];
        qW1 = (const float*)d_in[16]; qb1 = (const float*)d_in[17];
        qW2 = (const float*)d_in[18]; qb2 = (const float*)d_in[19];
        qW3 = (const float*)d_in[20]; qb3 = (const float*)d_in[21];
        edge_index = (const int*)d_in[22];
    }

    const int SMEM_MMA = 2 * 128 * SPITCH * 2;                        // 69632
    const int SMEM_H   = (16 * 516 + 2 * 16 * 128 + 3 * 128) * 4;     // 50944
    cudaFuncSetAttribute(k_gemm_mma, cudaFuncAttributeMaxDynamicSharedMemorySize, SMEM_MMA);
    cudaFuncSetAttribute(k_head,     cudaFuncAttributeMaxDynamicSharedMemorySize, SMEM_H);

    k_prep<<<Nn * 32 / 256, 256>>>(x, Wn, bn, edge_index, edge_attr);  // 1
    k_wconv<<<64, 256>>>(gWl, gWr);                                    // 2
    k_gemm_mma<<<Nn / 128, 256, SMEM_MMA>>>(gbl, gbr);                 // 3
    k_scan1<<<256, 256>>>();                                           // 4
    k_scan2<<<1, 256>>>();                                             // 5
    k_scan3<<<64, 1024>>>();                                           // 6
    k_fill<<<Eg / 256, 256>>>(edge_index, edge_attr);                  // 7
    k_edge<<<Nn / 16, 256>>>(gWe, gatt, gb);                           // 8 (2 nodes/warp)

    for (int l = 1; l < Lg; l++) {
        k_wconv<<<64, 256>>>(gWl + l * HIDN * HIDN, gWr + l * HIDN * HIDN);
        k_gemm_mma<<<Nn / 128, 256, SMEM_MMA>>>(gbl + l * HIDN, gbr + l * HIDN);
        k_edge<<<Nn / 16, 256>>>(gWe + l * HIDN, gatt + l * HIDN, gb + l * HIDN);
    }

    k_pool<<<Bg * 8, 128>>>();
    k_head<<<Bg * 2, 256, SMEM_H>>>(action_tensor, aW1, ab1, aW2, ab2,
                                    qW1, qb1, qW2, qb2, qW3, qb3, (float*)d_out);
}

// round 15
// speedup vs baseline: 1.0513x; 1.0513x over previous
#include <cuda_runtime.h>
#include <cuda_fp16.h>
#include <math.h>
#include <stdint.h>

#define Nn   65536
#define Bg   64
#define NPG  1024
#define Ag   32
#define HIDN 128
#define Eg   262144
#define Lg   3
#define NEG  0.2f

// ---------------- scratch (device globals; no allocation allowed) ----------------
// g_deg relies on BSS zero-init for the first call; k_scan1 re-zeroes after use.
__device__ float  g_h[Nn * HIDN];
__device__ __half g_xlh[Nn * HIDN];
__device__ __half g_xrh[Nn * HIDN];
__device__ __half g_w1h[HIDN * HIDN];
__device__ __half g_w2h[HIDN * HIDN];
__device__ int    g_indptr[Nn + 1];
__device__ int    g_cursor[Nn];
__device__ int    g_deg[Nn];
__device__ int    g_blocksum[256];
__device__ int    g_blockoff[256];
__device__ int2   g_csr[Eg];          // (src, ea bits) packed
__device__ float  g_partial[1024];
__device__ float  g_ea_mean;
__device__ float  g_pool_sum[Bg * HIDN];
__device__ float  g_pool_max[Bg * HIDN];

__device__ __forceinline__ float4 h4_to_f4(uint2 u) {
    __half2 a = *(__half2*)&u.x;
    __half2 b = *(__half2*)&u.y;
    float2 fa = __half22float2(a);
    float2 fb = __half22float2(b);
    return make_float4(fa.x, fa.y, fb.x, fb.y);
}
__device__ __forceinline__ void cp16(uint32_t dst, const void* src) {
    asm volatile("cp.async.cg.shared.global [%0], [%1], 16;" :: "r"(dst), "l"(src));
}

// ---------------- launch 1: fused h0-init + degree histogram + edge_attr mean ----------------
__global__ void k_prep(const float* __restrict__ x, const float* __restrict__ Wn,
                       const float* __restrict__ bn,
                       const int* __restrict__ ei, const float* __restrict__ ea) {
    int idx = blockIdx.x * 256 + threadIdx.x;
    {
        int node = idx >> 5;
        int c = (idx & 31) << 2;
        float xv = x[node];
        float4 w = *(const float4*)(Wn + c);
        float4 b = *(const float4*)(bn + c);
        float4 o;
        o.x = fmaxf(fmaf(xv, w.x, b.x), 0.f);
        o.y = fmaxf(fmaf(xv, w.y, b.y), 0.f);
        o.z = fmaxf(fmaf(xv, w.z, b.z), 0.f);
        o.w = fmaxf(fmaf(xv, w.w, b.w), 0.f);
        *(float4*)(g_h + node * HIDN + c) = o;
    }
    if (blockIdx.x < Eg / 256) {
        __shared__ float red[256];
        atomicAdd(&g_deg[ei[Eg + idx]], 1);
        red[threadIdx.x] = ea[idx];
        __syncthreads();
        for (int st = 128; st > 0; st >>= 1) {
            if (threadIdx.x < st) red[threadIdx.x] += red[threadIdx.x + st];
            __syncthreads();
        }
        if (threadIdx.x == 0) g_partial[blockIdx.x] = red[0];
    }
}

// ---------------- W converter: W[k][n] -> WT[n][k] fp16 ----------------
__global__ void k_wconv(const float* __restrict__ W1, const float* __restrict__ W2) {
    int idx = blockIdx.x * 256 + threadIdx.x;
    int k = idx >> 7, n = idx & 127;
    g_w1h[n * HIDN + k] = __float2half(W1[idx]);
    g_w2h[n * HIDN + k] = __float2half(W2[idx]);
}

// ---------------- HMMA dual GEMM, cp.async staging + overlapped restage (2 CTAs/SM) ----------------
#define SPITCH 136
__global__ __launch_bounds__(256, 2) void k_gemm_mma(const float* __restrict__ b1,
                                                     const float* __restrict__ b2) {
    extern __shared__ __half smh[];
    __half* sA = smh;                    // [128][136]
    __half* sB = sA + 128 * SPITCH;      // [128][136]

    const int tid  = threadIdx.x;
    const int row0 = blockIdx.x * 128;
    const int srow = tid >> 1, sc0 = (tid & 1) * 64;

    uint32_t smem_u32;
    asm("{ .reg .u64 t; cvta.to.shared.u64 t, %1; cvt.u32.u64 %0, t; }"
        : "=r"(smem_u32) : "l"(smh));
    const uint32_t aBase = smem_u32;
    const uint32_t bBase = smem_u32 + 128 * SPITCH * 2;
    const uint32_t bRowAddr = bBase + (uint32_t)(srow * SPITCH + sc0) * 2;

    {
        const __half* s1 = g_w1h + srow * HIDN + sc0;
        #pragma unroll
        for (int j = 0; j < 64; j += 8)
            cp16(bRowAddr + j * 2, s1 + j);
        asm volatile("cp.async.commit_group;");

        const float* srcA = g_h + (size_t)(row0 + srow) * HIDN + sc0;
        __half* dA = sA + srow * SPITCH + sc0;
        #pragma unroll
        for (int j = 0; j < 64; j += 8) {
            float4 f0 = *(const float4*)(srcA + j);
            float4 f1 = *(const float4*)(srcA + j + 4);
            uint4 u;
            *(__half2*)&u.x = __floats2half2_rn(f0.x, f0.y);
            *(__half2*)&u.y = __floats2half2_rn(f0.z, f0.w);
            *(__half2*)&u.z = __floats2half2_rn(f1.x, f1.y);
            *(__half2*)&u.w = __floats2half2_rn(f1.z, f1.w);
            *(uint4*)(dA + j) = u;
        }
        asm volatile("cp.async.wait_group 0;");
    }
    __syncthreads();

    const int warp = tid >> 5, lane = tid & 31;
    const int mrow = (warp & 3) * 32;
    const int ncol = (warp >> 2) * 64;

    const int l7   = lane & 7;
    const int rsel = ((lane >> 3) & 1) * 8;
    const int csel = (lane >> 4) * 8;
    uint32_t aOff[2];
    #pragma unroll
    for (int m = 0; m < 2; m++)
        aOff[m] = aBase + (uint32_t)((mrow + m * 16 + l7 + rsel) * SPITCH + csel) * 2;
    const int bRow = l7 + (lane >> 4) * 8;
    const int bCol = ((lane >> 3) & 1) * 8;
    uint32_t bOff[4];
    #pragma unroll
    for (int np = 0; np < 4; np++)
        bOff[np] = bBase + (uint32_t)((ncol + np * 16 + bRow) * SPITCH + bCol) * 2;

    #pragma unroll
    for (int mat = 0; mat < 2; mat++) {
        const float* bias = mat ? b2 : b1;
        __half* dst       = mat ? g_xrh : g_xlh;

        float acc[2][8][4];
        #pragma unroll
        for (int m = 0; m < 2; m++)
            #pragma unroll
            for (int n = 0; n < 8; n++)
                #pragma unroll
                for (int q = 0; q < 4; q++) acc[m][n][q] = 0.f;

        #pragma unroll
        for (int k0 = 0; k0 < 128; k0 += 16) {
            uint32_t a[2][4];
            #pragma unroll
            for (int m = 0; m < 2; m++)
                asm volatile("ldmatrix.sync.aligned.m8n8.x4.shared.b16 {%0,%1,%2,%3}, [%4];"
                    : "=r"(a[m][0]), "=r"(a[m][1]), "=r"(a[m][2]), "=r"(a[m][3])
                    : "r"(aOff[m] + k0 * 2));
            uint32_t b[8][2];
            #pragma unroll
            for (int np = 0; np < 4; np++) {
                uint32_t r0, r1, r2, r3;
                asm volatile("ldmatrix.sync.aligned.m8n8.x4.shared.b16 {%0,%1,%2,%3}, [%4];"
                    : "=r"(r0), "=r"(r1), "=r"(r2), "=r"(r3)
                    : "r"(bOff[np] + k0 * 2));
                b[np * 2][0] = r0; b[np * 2][1] = r1;
                b[np * 2 + 1][0] = r2; b[np * 2 + 1][1] = r3;
            }
            #pragma unroll
            for (int m = 0; m < 2; m++)
                #pragma unroll
                for (int n = 0; n < 8; n++)
                    asm volatile(
                        "mma.sync.aligned.m16n8k16.row.col.f32.f16.f16.f32 "
                        "{%0,%1,%2,%3}, {%4,%5,%6,%7}, {%8,%9}, {%0,%1,%2,%3};"
                        : "+f"(acc[m][n][0]), "+f"(acc[m][n][1]),
                          "+f"(acc[m][n][2]), "+f"(acc[m][n][3])
                        : "r"(a[m][0]), "r"(a[m][1]), "r"(a[m][2]), "r"(a[m][3]),
                          "r"(b[n][0]), "r"(b[n][1]));
        }

        if (mat == 0) {
            __syncthreads();
            const __half* s2 = g_w2h + srow * HIDN + sc0;
            #pragma unroll
            for (int j = 0; j < 64; j += 8)
                cp16(bRowAddr + j * 2, s2 + j);
            asm volatile("cp.async.commit_group;");
        }

        const int gid = lane >> 2, t4 = lane & 3;
        #pragma unroll
        for (int m = 0; m < 2; m++) {
            #pragma unroll
            for (int n = 0; n < 8; n++) {
                int col = ncol + n * 8 + t4 * 2;
                float bx = __ldg(&bias[col]), by = __ldg(&bias[col + 1]);
                int r0w = row0 + mrow + m * 16 + gid;
                *(__half2*)(dst + (size_t)r0w * HIDN + col) =
                    __floats2half2_rn(acc[m][n][0] + bx, acc[m][n][1] + by);
                *(__half2*)(dst + (size_t)(r0w + 8) * HIDN + col) =
                    __floats2half2_rn(acc[m][n][2] + bx, acc[m][n][3] + by);
            }
        }

        if (mat == 0) {
            asm volatile("cp.async.wait_group 0;");
            __syncthreads();
        }
    }
}

// ---------------- scan stage 1 ----------------
__global__ void k_scan1() {
    __shared__ int sc[256];
    int node = blockIdx.x * 256 + threadIdx.x;
    int d = g_deg[node];
    g_deg[node] = 0;
    sc[threadIdx.x] = d;
    __syncthreads();
    for (int off = 1; off < 256; off <<= 1) {
        int v = (threadIdx.x >= off) ? sc[threadIdx.x - off] : 0;
        __syncthreads();
        sc[threadIdx.x] += v;
        __syncthreads();
    }
    g_cursor[node] = sc[threadIdx.x] - d;
    if (threadIdx.x == 255) g_blocksum[blockIdx.x] = sc[255];
}

// ---------------- scan stage 2 ----------------
__global__ void k_scan2() {
    __shared__ int   sc[256];
    __shared__ float red[256];
    int t = threadIdx.x;
    int d = g_blocksum[t];
    sc[t] = d;
    float fs = g_partial[t] + g_partial[t + 256] + g_partial[t + 512] + g_partial[t + 768];
    red[t] = fs;
    __syncthreads();
    for (int off = 1; off < 256; off <<= 1) {
        int v = (t >= off) ? sc[t - off] : 0;
        __syncthreads();
        sc[t] += v;
        __syncthreads();
    }
    g_blockoff[t] = sc[t] - d;
    for (int st = 128; st > 0; st >>= 1) {
        if (t < st) red[t] += red[t + st];
        __syncthreads();
    }
    if (t == 0) g_ea_mean = red[0] / (float)Eg;
}

// ---------------- scan stage 3 ----------------
__global__ void k_scan3() {
    int idx = blockIdx.x * 1024 + threadIdx.x;
    int v = g_cursor[idx] + g_blockoff[idx >> 8];
    g_indptr[idx] = v;
    g_cursor[idx] = v;
    if (idx == 0) g_indptr[Nn] = Eg;
}

// ---------------- CSR fill (packed int2) + zero pool accumulators ----------------
__global__ void k_fill(const int* __restrict__ ei, const float* __restrict__ ea) {
    int e = blockIdx.x * blockDim.x + threadIdx.x;
    if (e < Bg * HIDN) { g_pool_sum[e] = 0.f; g_pool_max[e] = 0.f; }
    if (e < Eg) {
        int d = ei[Eg + e];
        int pos = atomicAdd(&g_cursor[d], 1);
        g_csr[pos] = make_int2(ei[e], __float_as_int(ea[e]));
    }
}

// ---------------- edge aggregation (round-13 proven + packed CSR) ----------------
__global__ __launch_bounds__(256) void k_edge(const float* __restrict__ We,
                                              const float* __restrict__ att,
                                              const float* __restrict__ gb) {
    int node = (blockIdx.x * blockDim.x + threadIdx.x) >> 5;
    int lane = threadIdx.x & 31;
    if (node >= Nn) return;
    const int base = ((lane >> 3) << 5) + ((lane & 7) << 2);

    const float4 We4  = *(const float4*)(We + base);
    const float4 att4 = *(const float4*)(att + base);
    const float4 xr4  = h4_to_f4(*(const uint2*)(g_xrh + (size_t)node * HIDN + base));
    const float4 xl4  = h4_to_f4(*(const uint2*)(g_xlh + (size_t)node * HIDN + base));
    const float  eam  = g_ea_mean;

    const int e0 = g_indptr[node], e1 = g_indptr[node + 1];
    const int npairs = (e1 - e0) >> 1;

    // prefetch first pair before the (independent) self-logit chain
    uint2 xu0 = make_uint2(0u, 0u), xu1 = make_uint2(0u, 0u);
    float a0 = 0.f, a1 = 0.f;
    if (npairs > 0) {
        int2 c0 = g_csr[e0], c1 = g_csr[e0 + 1];
        a0 = __int_as_float(c0.y); a1 = __int_as_float(c1.y);
        xu0 = __ldg((const uint2*)(g_xlh + (size_t)c0.x * HIDN + base));
        xu1 = __ldg((const uint2*)(g_xlh + (size_t)c1.x * HIDN + base));
    }

    // self-loop logit -> fixed offset m
    float m;
    {
        float v0 = fmaf(eam, We4.x, xl4.x + xr4.x); v0 = v0 > 0.f ? v0 : NEG * v0;
        float v1 = fmaf(eam, We4.y, xl4.y + xr4.y); v1 = v1 > 0.f ? v1 : NEG * v1;
        float v2 = fmaf(eam, We4.z, xl4.z + xr4.z); v2 = v2 > 0.f ? v2 : NEG * v2;
        float v3 = fmaf(eam, We4.w, xl4.w + xr4.w); v3 = v3 > 0.f ? v3 : NEG * v3;
        float p = v0 * att4.x;
        p = fmaf(v1, att4.y, p);
        p = fmaf(v2, att4.z, p);
        p = fmaf(v3, att4.w, p);
        p += __shfl_xor_sync(0xffffffffu, p, 4);
        p += __shfl_xor_sync(0xffffffffu, p, 2);
        p += __shfl_xor_sync(0xffffffffu, p, 1);
        m = p;
    }
    float  s   = 1.f;
    float4 acc = xl4;

    int e = e0;
    for (int i = 0; i < npairs; i++) {
        // prefetch next pair — overlaps the compute chain below
        uint2 nxu0 = make_uint2(0u, 0u), nxu1 = make_uint2(0u, 0u);
        float na0 = 0.f, na1 = 0.f;
        if (i + 1 < npairs) {
            int2 c0 = g_csr[e + 2], c1 = g_csr[e + 3];
            na0 = __int_as_float(c0.y); na1 = __int_as_float(c1.y);
            nxu0 = __ldg((const uint2*)(g_xlh + (size_t)c0.x * HIDN + base));
            nxu1 = __ldg((const uint2*)(g_xlh + (size_t)c1.x * HIDN + base));
        }

        float4 x0 = h4_to_f4(xu0);
        float4 x1 = h4_to_f4(xu1);

        float v, q0, q1;
        v = fmaf(a0, We4.x, x0.x + xr4.x); v = v > 0.f ? v : NEG * v; q0 = v * att4.x;
        v = fmaf(a0, We4.y, x0.y + xr4.y); v = v > 0.f ? v : NEG * v; q0 = fmaf(v, att4.y, q0);
        v = fmaf(a0, We4.z, x0.z + xr4.z); v = v > 0.f ? v : NEG * v; q0 = fmaf(v, att4.z, q0);
        v = fmaf(a0, We4.w, x0.w + xr4.w); v = v > 0.f ? v : NEG * v; q0 = fmaf(v, att4.w, q0);
        v = fmaf(a1, We4.x, x1.x + xr4.x); v = v > 0.f ? v : NEG * v; q1 = v * att4.x;
        v = fmaf(a1, We4.y, x1.y + xr4.y); v = v > 0.f ? v : NEG * v; q1 = fmaf(v, att4.y, q1);
        v = fmaf(a1, We4.z, x1.z + xr4.z); v = v > 0.f ? v : NEG * v; q1 = fmaf(v, att4.z, q1);
        v = fmaf(a1, We4.w, x1.w + xr4.w); v = v > 0.f ? v : NEG * v; q1 = fmaf(v, att4.w, q1);

        q0 += __shfl_xor_sync(0xffffffffu, q0, 4);
        q1 += __shfl_xor_sync(0xffffffffu, q1, 4);
        q0 += __shfl_xor_sync(0xffffffffu, q0, 2);
        q1 += __shfl_xor_sync(0xffffffffu, q1, 2);
        q0 += __shfl_xor_sync(0xffffffffu, q0, 1);
        q1 += __shfl_xor_sync(0xffffffffu, q1, 1);

        float p0 = __expf(q0 - m);
        float p1 = __expf(q1 - m);
        s += p0 + p1;
        acc.x = fmaf(p0, x0.x, fmaf(p1, x1.x, acc.x));
        acc.y = fmaf(p0, x0.y, fmaf(p1, x1.y, acc.y));
        acc.z = fmaf(p0, x0.z, fmaf(p1, x1.z, acc.z));
        acc.w = fmaf(p0, x0.w, fmaf(p1, x1.w, acc.w));

        xu0 = nxu0; xu1 = nxu1; a0 = na0; a1 = na1;
        e += 2;
    }
    if (e < e1) {
        int2 c0 = g_csr[e];
        float ta = __int_as_float(c0.y);
        float4 x0 = h4_to_f4(__ldg((const uint2*)(g_xlh + (size_t)c0.x * HIDN + base)));
        float v, q0;
        v = fmaf(ta, We4.x, x0.x + xr4.x); v = v > 0.f ? v : NEG * v; q0 = v * att4.x;
        v = fmaf(ta, We4.y, x0.y + xr4.y); v = v > 0.f ? v : NEG * v; q0 = fmaf(v, att4.y, q0);
        v = fmaf(ta, We4.z, x0.z + xr4.z); v = v > 0.f ? v : NEG * v; q0 = fmaf(v, att4.z, q0);
        v = fmaf(ta, We4.w, x0.w + xr4.w); v = v > 0.f ? v : NEG * v; q0 = fmaf(v, att4.w, q0);
        q0 += __shfl_xor_sync(0xffffffffu, q0, 4);
        q0 += __shfl_xor_sync(0xffffffffu, q0, 2);
        q0 += __shfl_xor_sync(0xffffffffu, q0, 1);
        float p0 = __expf(q0 - m);
        s += p0;
        acc.x = fmaf(p0, x0.x, acc.x);
        acc.y = fmaf(p0, x0.y, acc.y);
        acc.z = fmaf(p0, x0.z, acc.z);
        acc.w = fmaf(p0, x0.w, acc.w);
    }

    const float inv = 1.f / s;
    const float4 gb4 = *(const float4*)(gb + base);
    const float4 h4  = *(const float4*)(g_h + (size_t)node * HIDN + base);
    float4 o;
    o.x = fmaxf(fmaf(acc.x, inv, gb4.x), 0.f) + h4.x;
    o.y = fmaxf(fmaf(acc.y, inv, gb4.y), 0.f) + h4.y;
    o.z = fmaxf(fmaf(acc.z, inv, gb4.z), 0.f) + h4.z;
    o.w = fmaxf(fmaf(acc.w, inv, gb4.w), 0.f) + h4.w;
    *(float4*)(g_h + (size_t)node * HIDN + base) = o;
}

// ---------------- pooling (h >= 0, int-bit atomicMax valid) ----------------
__global__ void k_pool() {
    int b = blockIdx.x >> 3;
    int chunk = blockIdx.x & 7;
    int j = threadIdx.x;
    int node0 = b * NPG + chunk * 128;
    float s = 0.f, mx = 0.f;
    #pragma unroll 4
    for (int t = 0; t < 128; t++) {
        float v = g_h[(size_t)(node0 + t) * HIDN + j];
        s += v;
        mx = fmaxf(mx, v);
    }
    atomicAdd(&g_pool_sum[b * HIDN + j], s);
    atomicMax((int*)&g_pool_max[b * HIDN + j], __float_as_int(mx));
}

// ---------------- fused action encoder + Q head ----------------
__global__ __launch_bounds__(256) void k_head(const float* __restrict__ at,
        const float* __restrict__ aW1, const float* __restrict__ ab1,
        const float* __restrict__ aW2, const float* __restrict__ ab2,
        const float* __restrict__ qW1, const float* __restrict__ qb1,
        const float* __restrict__ qW2, const float* __restrict__ qb2,
        const float* __restrict__ qW3, const float* __restrict__ qb3,
        float* __restrict__ out) {
    extern __shared__ float sm[];
    float* IN   = sm;
    float* S1   = IN + 16 * 516;
    float* S2   = S1 + 16 * 128;
    float* tcol = S2 + 16 * 128;
    float* ps   = tcol + 128;
    float* pm   = ps + 128;

    const int tid = threadIdx.x;
    const int b   = blockIdx.x >> 1;
    const int a0  = (blockIdx.x & 1) * 16;

    if (tid < 128) {
        ps[tid] = g_pool_sum[b * HIDN + tid];
        pm[tid] = g_pool_max[b * HIDN + tid];
    }
    __syncthreads();

    for (int idx = tid; idx < 16 * 512; idx += 256) {
        int a = idx >> 9, q = idx & 511;
        int slot = q >> 7, col = q & 127;
        int node = (int)at[(size_t)(b * Ag + a0 + a) * 7 + slot] + b * NPG;
        IN[a * 516 + q] = g_h[(size_t)node * HIDN + col];
    }
    for (int idx = tid; idx < 16 * 3; idx += 256) {
        int a = idx / 3, ms = idx % 3;
        IN[a * 516 + 512 + ms] = at[(size_t)(b * Ag + a0 + a) * 7 + 4 + ms];
    }
    if (tid < 128) {
        float acc = qb1[tid];
        for (int k = 0; k < 128; k++) {
            float sv = ps[k];
            acc = fmaf(sv, qW1[k * 128 + tid], acc);
            acc = fmaf(sv * (1.f / 1024.f), qW1[(128 + k) * 128 + tid], acc);
            acc = fmaf(pm[k], qW1[(256 + k) * 128 + tid], acc);
        }
        tcol[tid] = acc;
    }
    __syncthreads();

    const int col = tid & 127;
    const int ab  = (tid >> 7) * 8;

    {
        float acc[8]; float bias = ab1[col];
        #pragma unroll
        for (int a = 0; a < 8; a++) acc[a] = bias;
        for (int k = 0; k < 515; k++) {
            float w = aW1[k * 128 + col];
            #pragma unroll
            for (int a = 0; a < 8; a++) acc[a] = fmaf(IN[(ab + a) * 516 + k], w, acc[a]);
        }
        #pragma unroll
        for (int a = 0; a < 8; a++) S1[(ab + a) * 128 + col] = fmaxf(acc[a], 0.f);
    }
    __syncthreads();
    {
        float acc[8]; float bias = ab2[col];
        #pragma unroll
        for (int a = 0; a < 8; a++) acc[a] = bias;
        for (int k = 0; k < 128; k++) {
            float w = aW2[k * 128 + col];
            #pragma unroll
            for (int a = 0; a < 8; a++) acc[a] = fmaf(S1[(ab + a) * 128 + k], w, acc[a]);
        }
        #pragma unroll
        for (int a = 0; a < 8; a++) S2[(ab + a) * 128 + col] = fmaxf(acc[a], 0.f);
    }
    __syncthreads();
    {
        float acc[8]; float t = tcol[col];
        #pragma unroll
        for (int a = 0; a < 8; a++) acc[a] = t;
        for (int k = 0; k < 128; k++) {
            float w = qW1[(384 + k) * 128 + col];
            #pragma unroll
            for (int a = 0; a < 8; a++) acc[a] = fmaf(S2[(ab + a) * 128 + k], w, acc[a]);
        }
        #pragma unroll
        for (int a = 0; a < 8; a++) S1[(ab + a) * 128 + col] = fmaxf(acc[a], 0.f);
    }
    __syncthreads();
    {
        float acc[8]; float bias = qb2[col];
        #pragma unroll
        for (int a = 0; a < 8; a++) acc[a] = bias;
        for (int k = 0; k < 128; k++) {
            float w = qW2[k * 128 + col];
            #pragma unroll
            for (int a = 0; a < 8; a++) acc[a] = fmaf(S1[(ab + a) * 128 + k], w, acc[a]);
        }
        #pragma unroll
        for (int a = 0; a < 8; a++) S2[(ab + a) * 128 + col] = fmaxf(acc[a], 0.f);
    }
    __syncthreads();
    {
        int w_id = tid >> 5, lane = tid & 31;
        for (int a = w_id; a < 16; a += 8) {
            float s = 0.f;
            #pragma unroll
            for (int kk = 0; kk < 4; kk++)
                s = fmaf(S2[a * 128 + kk * 32 + lane], qW3[kk * 32 + lane], s);
            #pragma unroll
            for (int o = 16; o > 0; o >>= 1) s += __shfl_xor_sync(0xffffffffu, s, o);
            if (lane == 0) out[b * Ag + a0 + a] = s + qb3[0];
        }
    }
}

// ---------------- launch ----------------
extern "C" void kernel_launch(void* const* d_in, const int* in_sizes, int n_in,
                              void* d_out, int out_size) {
    const float *x, *edge_attr, *action_tensor;
    const float *Wn, *bn, *gWl, *gbl, *gWr, *gbr, *gWe, *gatt, *gb;
    const float *aW1, *ab1, *aW2, *ab2, *qW1, *qb1, *qW2, *qb2, *qW3, *qb3;
    const int* edge_index;

    x             = (const float*)d_in[0];
    edge_attr     = (const float*)d_in[1];
    action_tensor = (const float*)d_in[2];

    if (in_sizes[3] > 100000) {
        edge_index = (const int*)d_in[3];
        Wn  = (const float*)d_in[6];  bn  = (const float*)d_in[7];
        gWl = (const float*)d_in[8];  gWr = (const float*)d_in[9];
        gWe = (const float*)d_in[10]; gatt= (const float*)d_in[11];
        gbl = (const float*)d_in[12]; gbr = (const float*)d_in[13];
        gb  = (const float*)d_in[14];
        aW1 = (const float*)d_in[15]; ab1 = (const float*)d_in[16];
        aW2 = (const float*)d_in[17]; ab2 = (const float*)d_in[18];
        qW1 = (const float*)d_in[19]; qb1 = (const float*)d_in[20];
        qW2 = (const float*)d_in[21]; qb2 = (const float*)d_in[22];
        qW3 = (const float*)d_in[23]; qb3 = (const float*)d_in[24];
    } else {
        Wn  = (const float*)d_in[3];  bn  = (const float*)d_in[4];
        gWl = (const float*)d_in[5];  gbl = (const float*)d_in[6];
        gWr = (const float*)d_in[7];  gbr = (const float*)d_in[8];
        gWe = (const float*)d_in[9];  gatt= (const float*)d_in[10];
        gb  = (const float*)d_in[11];
        aW1 = (const float*)d_in[12]; ab1 = (const float*)d_in[13];
        aW2 = (const float*)d_in[14]; ab2 = (const float*)d_in[15];
        qW1 = (const float*)d_in[16]; qb1 = (const float*)d_in[17];
        qW2 = (const float*)d_in[18]; qb2 = (const float*)d_in[19];
        qW3 = (const float*)d_in[20]; qb3 = (const float*)d_in[21];
        edge_index = (const int*)d_in[22];
    }

    const int SMEM_MMA = 2 * 128 * SPITCH * 2;                        // 69632
    const int SMEM_H   = (16 * 516 + 2 * 16 * 128 + 3 * 128) * 4;     // 50944
    cudaFuncSetAttribute(k_gemm_mma, cudaFuncAttributeMaxDynamicSharedMemorySize, SMEM_MMA);
    cudaFuncSetAttribute(k_head,     cudaFuncAttributeMaxDynamicSharedMemorySize, SMEM_H);

    k_prep<<<Nn * 32 / 256, 256>>>(x, Wn, bn, edge_index, edge_attr);  // 1
    k_wconv<<<64, 256>>>(gWl, gWr);                                    // 2
    k_gemm_mma<<<Nn / 128, 256, SMEM_MMA>>>(gbl, gbr);                 // 3
    k_scan1<<<256, 256>>>();                                           // 4
    k_scan2<<<1, 256>>>();                                             // 5
    k_scan3<<<64, 1024>>>();                                           // 6
    k_fill<<<Eg / 256, 256>>>(edge_index, edge_attr);                  // 7
    k_edge<<<Nn / 8, 256>>>(gWe, gatt, gb);                            // 8

    for (int l = 1; l < Lg; l++) {
        k_wconv<<<64, 256>>>(gWl + l * HIDN * HIDN, gWr + l * HIDN * HIDN);
        k_gemm_mma<<<Nn / 128, 256, SMEM_MMA>>>(gbl + l * HIDN, gbr + l * HIDN);
        k_edge<<<Nn / 8, 256>>>(gWe + l * HIDN, gatt + l * HIDN, gb + l * HIDN);
    }

    k_pool<<<Bg * 8, 128>>>();
    k_head<<<Bg * 2, 256, SMEM_H>>>(action_tensor, aW1, ab1, aW2, ab2,
                                    qW1, qb1, qW2, qb2, qW3, qb3, (float*)d_out);
}